// round 3
// baseline (speedup 1.0000x reference)
#include <cuda_runtime.h>
#include <cuda_bf16.h>
#include <cstdint>

// FM-CTR kernel.
// Inputs (metadata order):
//  d_in[0]: dense_x     f32 [16384, 13]
//  d_in[1]: discrete_x  i32 [16384, 26]   (JAX default x64-disabled -> int32)
//  d_in[2]: emb_tables  f32 [26, 50000, 128]
//  d_in[3]: dense_w     f32 [128, 13]
//  d_in[4]: dense_b     f32 [128]
// Output: f32 [16384]
//
// 1 warp per batch row. Lane l owns float4 slice [4l,4l+4) of the 128-d
// embedding; each table gather = one coalesced 512B warp read. Indices are
// loaded by lanes 0..25 and broadcast via shfl so the 26 LDG.128 are
// address-independent (high MLP -> DRAM latency hidden).

#define N_TABLES 26
#define VOCAB    50000
#define EMBED_DIM 128
#define DENSE_DIM 13
#define BATCH    16384

__global__ __launch_bounds__(256) void fm_ctr_kernel(
    const float* __restrict__ dense_x,
    const int*   __restrict__ discrete_x,
    const float* __restrict__ emb,
    const float* __restrict__ dense_w,
    const float* __restrict__ dense_b,
    float* __restrict__ out)
{
    const int gwarp = (blockIdx.x * blockDim.x + threadIdx.x) >> 5;
    const int lane  = threadIdx.x & 31;
    if (gwarp >= BATCH) return;

    // Lanes 0..25 load one index each; broadcast below via shfl.
    int my_idx = 0;
    if (lane < N_TABLES)
        my_idx = discrete_x[(long long)gwarp * N_TABLES + lane];

    float4 s = make_float4(0.f, 0.f, 0.f, 0.f);   // sum of embeds (my 4 dims)
    float4 q = make_float4(0.f, 0.f, 0.f, 0.f);   // sum of squares

    #pragma unroll
    for (int t = 0; t < N_TABLES; t++) {
        int id = __shfl_sync(0xffffffffu, my_idx, t);
        const float4* row = reinterpret_cast<const float4*>(
            emb + ((long long)t * VOCAB + (long long)id) * EMBED_DIM);
        float4 v = __ldg(row + lane);
        s.x += v.x; s.y += v.y; s.z += v.z; s.w += v.w;
        q.x = fmaf(v.x, v.x, q.x);
        q.y = fmaf(v.y, v.y, q.y);
        q.z = fmaf(v.z, v.z, q.z);
        q.w = fmaf(v.w, v.w, q.w);
    }

    // Dense embed: e[d] = sum_k dense_x[b,k] * dense_w[d,k] + dense_b[d]
    // Lane l owns d = 4l .. 4l+3. Weights/bias are tiny and L1/L2 resident.
    float xr[DENSE_DIM];
    #pragma unroll
    for (int k = 0; k < DENSE_DIM; k++)
        xr[k] = __ldg(dense_x + (long long)gwarp * DENSE_DIM + k);

    #pragma unroll
    for (int j = 0; j < 4; j++) {
        int d = 4 * lane + j;
        float e = __ldg(dense_b + d);
        #pragma unroll
        for (int k = 0; k < DENSE_DIM; k++)
            e = fmaf(xr[k], __ldg(dense_w + d * DENSE_DIM + k), e);
        if (j == 0) { s.x += e; q.x = fmaf(e, e, q.x); }
        if (j == 1) { s.y += e; q.y = fmaf(e, e, q.y); }
        if (j == 2) { s.z += e; q.z = fmaf(e, e, q.z); }
        if (j == 3) { s.w += e; q.w = fmaf(e, e, q.w); }
    }

    // FM partial for my 4 dims: 0.5 * (S^2 - sumsq)
    float fm = 0.5f * ((s.x * s.x - q.x) + (s.y * s.y - q.y) +
                       (s.z * s.z - q.z) + (s.w * s.w - q.w));

    // Warp reduction.
    #pragma unroll
    for (int o = 16; o > 0; o >>= 1)
        fm += __shfl_down_sync(0xffffffffu, fm, o);

    if (lane == 0) out[gwarp] = fm;
}

extern "C" void kernel_launch(void* const* d_in, const int* in_sizes, int n_in,
                              void* d_out, int out_size)
{
    const float* dense_x    = (const float*)d_in[0];
    const int*   discrete_x = (const int*)d_in[1];
    const float* emb        = (const float*)d_in[2];
    const float* dense_w    = (const float*)d_in[3];
    const float* dense_b    = (const float*)d_in[4];
    float* out = (float*)d_out;

    const int threads = 256;                 // 8 warps / block
    const int rows_per_block = threads / 32;
    const int blocks = (BATCH + rows_per_block - 1) / rows_per_block;
    fm_ctr_kernel<<<blocks, threads>>>(dense_x, discrete_x, emb,
                                       dense_w, dense_b, out);
}

// round 5
// speedup vs baseline: 1.0360x; 1.0360x over previous
#include <cuda_runtime.h>
#include <cuda_bf16.h>
#include <cstdint>

// FM-CTR kernel — R5: chunked two-phase gathers for guaranteed MLP.
// Inputs (metadata order):
//  d_in[0]: dense_x     f32 [16384, 13]
//  d_in[1]: discrete_x  i32 [16384, 26]
//  d_in[2]: emb_tables  f32 [26, 50000, 128]
//  d_in[3]: dense_w     f32 [128, 13]
//  d_in[4]: dense_b     f32 [128]
// Output: f32 [16384]
//
// 1 warp per batch row; lane l owns float4 slice [4l,4l+4) of the 128-d
// embedding (each table gather = one coalesced 512B warp read).
// Gathers are issued in 2 chunks of 13 into explicit register arrays so
// ptxas front-batches 13 address-independent LDG.128s per chunk
// (MLP_p1 >= 13), hiding DRAM latency. Dense matvec is computed under the
// shadow of chunk 2's loads.

#define N_TABLES 26
#define VOCAB    50000
#define EMBED_DIM 128
#define DENSE_DIM 13
#define BATCH    16384
#define CHUNK    13

__global__ __launch_bounds__(256) void fm_ctr_kernel(
    const float* __restrict__ dense_x,
    const int*   __restrict__ discrete_x,
    const float* __restrict__ emb,
    const float* __restrict__ dense_w,
    const float* __restrict__ dense_b,
    float* __restrict__ out)
{
    const int gwarp = (blockIdx.x * blockDim.x + threadIdx.x) >> 5;
    const int lane  = threadIdx.x & 31;
    if (gwarp >= BATCH) return;

    // Lanes 0..25 load one index each; broadcast below via shfl.
    int my_idx = 0;
    if (lane < N_TABLES)
        my_idx = discrete_x[(long long)gwarp * N_TABLES + lane];

    float4 s = make_float4(0.f, 0.f, 0.f, 0.f);   // sum of embeds (my 4 dims)
    float4 q = make_float4(0.f, 0.f, 0.f, 0.f);   // sum of squares

    // ---- Chunk 1: issue 13 independent gathers, then consume ----
    float4 v[CHUNK];
    #pragma unroll
    for (int t = 0; t < CHUNK; t++) {
        int id = __shfl_sync(0xffffffffu, my_idx, t);
        const float4* row = reinterpret_cast<const float4*>(
            emb + ((long long)t * VOCAB + (long long)id) * EMBED_DIM);
        v[t] = __ldg(row + lane);
    }
    #pragma unroll
    for (int t = 0; t < CHUNK; t++) {
        s.x += v[t].x; s.y += v[t].y; s.z += v[t].z; s.w += v[t].w;
        q.x = fmaf(v[t].x, v[t].x, q.x);
        q.y = fmaf(v[t].y, v[t].y, q.y);
        q.z = fmaf(v[t].z, v[t].z, q.z);
        q.w = fmaf(v[t].w, v[t].w, q.w);
    }

    // ---- Chunk 2: issue 13 gathers ----
    #pragma unroll
    for (int t = 0; t < CHUNK; t++) {
        int tt = CHUNK + t;
        int id = __shfl_sync(0xffffffffu, my_idx, tt);
        const float4* row = reinterpret_cast<const float4*>(
            emb + ((long long)tt * VOCAB + (long long)id) * EMBED_DIM);
        v[t] = __ldg(row + lane);
    }

    // Dense matvec under the shadow of chunk 2's in-flight loads.
    // e[d] = sum_k dense_x[b,k] * dense_w[d,k] + dense_b[d]; lane owns d=4l..4l+3.
    float xr[DENSE_DIM];
    #pragma unroll
    for (int k = 0; k < DENSE_DIM; k++)
        xr[k] = __ldg(dense_x + (long long)gwarp * DENSE_DIM + k);

    float e0 = __ldg(dense_b + 4 * lane + 0);
    float e1 = __ldg(dense_b + 4 * lane + 1);
    float e2 = __ldg(dense_b + 4 * lane + 2);
    float e3 = __ldg(dense_b + 4 * lane + 3);
    #pragma unroll
    for (int k = 0; k < DENSE_DIM; k++) {
        e0 = fmaf(xr[k], __ldg(dense_w + (4 * lane + 0) * DENSE_DIM + k), e0);
        e1 = fmaf(xr[k], __ldg(dense_w + (4 * lane + 1) * DENSE_DIM + k), e1);
        e2 = fmaf(xr[k], __ldg(dense_w + (4 * lane + 2) * DENSE_DIM + k), e2);
        e3 = fmaf(xr[k], __ldg(dense_w + (4 * lane + 3) * DENSE_DIM + k), e3);
    }
    s.x += e0; q.x = fmaf(e0, e0, q.x);
    s.y += e1; q.y = fmaf(e1, e1, q.y);
    s.z += e2; q.z = fmaf(e2, e2, q.z);
    s.w += e3; q.w = fmaf(e3, e3, q.w);

    // ---- Consume chunk 2 ----
    #pragma unroll
    for (int t = 0; t < CHUNK; t++) {
        s.x += v[t].x; s.y += v[t].y; s.z += v[t].z; s.w += v[t].w;
        q.x = fmaf(v[t].x, v[t].x, q.x);
        q.y = fmaf(v[t].y, v[t].y, q.y);
        q.z = fmaf(v[t].z, v[t].z, q.z);
        q.w = fmaf(v[t].w, v[t].w, q.w);
    }

    // FM partial for my 4 dims: 0.5 * (S^2 - sumsq)
    float fm = 0.5f * ((s.x * s.x - q.x) + (s.y * s.y - q.y) +
                       (s.z * s.z - q.z) + (s.w * s.w - q.w));

    // Warp reduction.
    #pragma unroll
    for (int o = 16; o > 0; o >>= 1)
        fm += __shfl_down_sync(0xffffffffu, fm, o);

    if (lane == 0) out[gwarp] = fm;
}

extern "C" void kernel_launch(void* const* d_in, const int* in_sizes, int n_in,
                              void* d_out, int out_size)
{
    const float* dense_x    = (const float*)d_in[0];
    const int*   discrete_x = (const int*)d_in[1];
    const float* emb        = (const float*)d_in[2];
    const float* dense_w    = (const float*)d_in[3];
    const float* dense_b    = (const float*)d_in[4];
    float* out = (float*)d_out;

    const int threads = 256;                 // 8 warps / block
    const int rows_per_block = threads / 32;
    const int blocks = (BATCH + rows_per_block - 1) / rows_per_block;
    fm_ctr_kernel<<<blocks, threads>>>(dense_x, discrete_x, emb,
                                       dense_w, dense_b, out);
}